// round 11
// baseline (speedup 1.0000x reference)
#include <cuda_runtime.h>
#include <cuda_fp16.h>
#include <cstdint>
#include <math.h>

// ---------------------------------------------------------------------------
// Problem constants
// ---------------------------------------------------------------------------
#define H     128
#define MSG   256
#define TM    64          // rows per tile
#define NPAIRS 148        // tile stride (CTA pairs)
#define NTHREADS 512
#define WSTB  784         // smem row stride bytes (K=384 halves = 768B + pad)

#define SLAB_BYTE (192 * WSTB)            // 150528 : 3 gates x 64 cols
#define A_BYTE    SLAB_BYTE
#define SMEM_BYTES (SLAB_BYTE + TM * WSTB) // 200704

#define CLONE_PT 160      // clone rows per tile-chunk (160*32 = 5120 f4 = 10/thr)
#define CLONE_V  10

// device scratch
__device__ half          g_Wih_h[384 * MSG];
__device__ half          g_Whh_h[384 * H];
__device__ half          g_X_h[(long)204800 * MSG];   // fp16 messages
__device__ unsigned char g_flag[1 << 20];

__device__ __forceinline__ void ldsm_x4(uint32_t* r, uint32_t addr) {
    asm volatile("ldmatrix.sync.aligned.m8n8.x4.shared.b16 {%0,%1,%2,%3}, [%4];"
                 : "=r"(r[0]), "=r"(r[1]), "=r"(r[2]), "=r"(r[3]) : "r"(addr));
}
__device__ __forceinline__ void mma_f16(float* d, const uint32_t* a,
                                        uint32_t b0, uint32_t b1) {
    asm("mma.sync.aligned.m16n8k16.row.col.f32.f16.f16.f32 "
        "{%0,%1,%2,%3}, {%4,%5,%6,%7}, {%8,%9}, {%0,%1,%2,%3};"
        : "+f"(d[0]), "+f"(d[1]), "+f"(d[2]), "+f"(d[3])
        : "r"(a[0]), "r"(a[1]), "r"(a[2]), "r"(a[3]), "r"(b0), "r"(b1));
}
__device__ __forceinline__ uint32_t pack_h2(float x, float y) {
    half2 h = __float22half2_rn(make_float2(x, y));
    return *(uint32_t*)&h;
}
__device__ __forceinline__ void cp16(uint32_t smem_addr, const void* gptr) {
    asm volatile("cp.async.ca.shared.global [%0], [%1], 16;"
                 :: "r"(smem_addr), "l"(gptr) : "memory");
}
#define CP_COMMIT() asm volatile("cp.async.commit_group;" ::: "memory")
#define CP_WAIT0()  asm volatile("cp.async.wait_group 0;" ::: "memory")

// ---------------------------------------------------------------------------
// Prep: zero flags, convert W and X to fp16
// ---------------------------------------------------------------------------
__global__ void prep_kernel(const float* __restrict__ W_ih,
                            const float* __restrict__ W_hh,
                            const float* __restrict__ X,
                            int n_nodes, int B) {
    long i = (long)blockIdx.x * blockDim.x + threadIdx.x;
    long stride = (long)gridDim.x * blockDim.x;
    for (long j = i; j < n_nodes; j += stride) g_flag[j] = 0;
    for (long j = i; j < 384 * MSG + 384 * H; j += stride) {
        if (j < 384 * MSG) g_Wih_h[j] = __float2half_rn(W_ih[j]);
        else               g_Whh_h[j - 384 * MSG] = __float2half_rn(W_hh[j - 384 * MSG]);
    }
    long nx = (long)B * MSG;
    for (long j = i; j < nx; j += stride) g_X_h[j] = __float2half_rn(X[j]);
}
__global__ void flag_kernel(const int* __restrict__ node_ids, int B) {
    int i = blockIdx.x * blockDim.x + threadIdx.x;
    if (i < B) g_flag[node_ids[i]] = 1;
}

// ---------------------------------------------------------------------------
// Persistent weight-resident GRU + interleaved flag-based clone.
// grid = 2*NPAIRS; ch = bid&1 -> gate-column half. 512 threads:
//   wr = wid>>3 (row group of 32), wn = wid&7 (8-col group within the half).
// ---------------------------------------------------------------------------
__global__ __launch_bounds__(NTHREADS, 1)
void gru_persist_kernel(const float* __restrict__ memory,
                        const float* __restrict__ last_update,
                        const int*   __restrict__ node_ids,
                        const float* __restrict__ ts,
                        const float* __restrict__ b_ih,
                        const float* __restrict__ b_hh,
                        float* __restrict__ out_mem,
                        float* __restrict__ out_lu,
                        int B, int ntiles, int n_nodes, int rows_per_cta)
{
    extern __shared__ char smc[];
    half* smh = (half*)smc;
    const uint32_t sh_base = (uint32_t)__cvta_generic_to_shared(smc);

    const int tid  = threadIdx.x;
    const int lane = tid & 31;
    const int wid  = tid >> 5;
    const int wr   = wid >> 3;          // 0..1
    const int wn   = wid & 7;           // 0..7
    const int gid  = lane >> 2;
    const int tig  = lane & 3;
    const int ch   = blockIdx.x & 1;
    const int tstart = blockIdx.x >> 1;

    const int colb = ch * 64 + wn * 8 + tig * 2;
    const float brz0 = b_ih[colb]           + b_hh[colb];
    const float brz1 = b_ih[colb + 1]       + b_hh[colb + 1];
    const float bzz0 = b_ih[128 + colb]     + b_hh[128 + colb];
    const float bzz1 = b_ih[128 + colb + 1] + b_hh[128 + colb + 1];
    const float bin0 = b_ih[256 + colb],     bin1 = b_ih[256 + colb + 1];
    const float bhn0 = b_hh[256 + colb],     bhn1 = b_hh[256 + colb + 1];

    // ---- weight slab: 192 rows x 784B, loaded once ----
    #pragma unroll
    for (int i = 0; i < 18; i++) {
        int idx = tid + i * NTHREADS;              // < 9216 16B-units
        int n = idx / 48, u = idx - n * 48;
        int wrow = ((n >> 6) << 7) + (ch << 6) + (n & 63);
        if (u < 32) cp16(sh_base + (uint32_t)(n * WSTB + u * 16),
                         g_Wih_h + (long)wrow * MSG + u * 8);
        else        cp16(sh_base + (uint32_t)(n * WSTB + 512 + (u - 32) * 16),
                         g_Whh_h + (long)wrow * H + (u - 32) * 8);
    }
    CP_COMMIT();

    // ---- first A tile fill (direct path) ----
    {
        #pragma unroll
        for (int i = 0; i < 4; i++) {              // X part via cp.async
            int idx = tid + i * NTHREADS;
            int r = idx >> 5, u = idx & 31;
            long grow = (long)tstart * TM + r; if (grow >= B) grow = B - 1;
            cp16(sh_base + (uint32_t)(A_BYTE + r * WSTB + u * 16),
                 g_X_h + grow * MSG + u * 8);
        }
        CP_COMMIT();
        #pragma unroll
        for (int i = 0; i < 4; i++) {              // h part via registers
            int idx = tid + i * NTHREADS;
            int r = idx >> 5, u = idx & 31;
            long grow = (long)tstart * TM + r; if (grow >= B) grow = B - 1;
            int node = node_ids[grow];
            float4 v = *((const float4*)(memory + (long)node * H) + u);
            *(uint2*)(smh + (A_BYTE + r * WSTB + 512) / 2 + u * 4) =
                make_uint2(pack_h2(v.x, v.y), pack_h2(v.z, v.w));
        }
        CP_WAIT0();
    }
    __syncthreads();

    // ldsm bases
    const int lane8 = lane & 7, laneA = lane & 15;
    const uint32_t aB0 = sh_base + (uint32_t)A_BYTE
                       + (uint32_t)(wr * 32 + laneA) * WSTB + (uint32_t)(lane >> 4) * 16;
    const uint32_t aB1 = aB0 + 16u * WSTB;
    const uint32_t bOff0 = sh_base + (uint32_t)((      wn * 8 + lane8) * WSTB) + (uint32_t)(lane >> 3) * 16;
    const uint32_t bOff1 = bOff0 + 64u * WSTB;
    const uint32_t bOff2 = bOff0 + 128u * WSTB;

    // clone slice bookkeeping
    const long slice0   = (long)blockIdx.x * rows_per_cta;
    const long slice_end = (slice0 + rows_per_cta < n_nodes) ? slice0 + rows_per_cta : n_nodes;
    const int  nchunks  = (int)((slice_end > slice0)
                          ? (slice_end - slice0 + CLONE_PT - 1) / CLONE_PT : 0);

    int tl = 0;
    for (int tile = tstart; tile < ntiles; tile += NPAIRS, tl++) {
        const int  next     = tile + NPAIRS;
        const bool has_next = next < ntiles;

        // (a) clone chunk LDG batch
        float4 cv[CLONE_V];
        uint32_t keep = 0;
        const long ck0 = slice0 + (long)tl * CLONE_PT;
        const long crows = (tl < nchunks)
                         ? ((slice_end - ck0 < CLONE_PT) ? slice_end - ck0 : CLONE_PT) : 0;
        const long ccount = crows * 32;
        #pragma unroll
        for (int i = 0; i < CLONE_V; i++) {
            long fi = tid + (long)i * NTHREADS;
            if (fi < ccount) {
                long row = ck0 + (fi >> 5);
                if (!g_flag[row]) {
                    keep |= (1u << i);
                    cv[i] = *((const float4*)(memory + row * H) + (fi & 31));
                }
            }
        }

        // (a2) next-tile h prefetch
        float4 ph[4];
        if (has_next) {
            #pragma unroll
            for (int i = 0; i < 4; i++) {
                int idx = tid + i * NTHREADS;
                int r = idx >> 5, u = idx & 31;
                long grow = (long)next * TM + r; if (grow >= B) grow = B - 1;
                int node = node_ids[grow];
                ph[i] = *((const float4*)(memory + (long)node * H) + u);
            }
        }

        // (a3) epilogue h prefetch
        int    hnode[4];
        float2 hv[4];
        #pragma unroll
        for (int mt = 0; mt < 2; mt++)
            #pragma unroll
            for (int sr = 0; sr < 2; sr++) {
                long grow = (long)tile * TM + wr * 32 + mt * 16 + gid + sr * 8;
                if (grow >= B) grow = B - 1;
                int node = node_ids[grow];
                hnode[mt * 2 + sr] = node;
                hv[mt * 2 + sr] = *(const float2*)(memory + (long)node * H + colb);
            }

        // (c) barrier-free K loop
        float acc[2][4][4];
        #pragma unroll
        for (int mt = 0; mt < 2; mt++)
            #pragma unroll
            for (int g = 0; g < 4; g++)
                #pragma unroll
                for (int j = 0; j < 4; j++) acc[mt][g][j] = 0.f;

        #pragma unroll
        for (int c = 0; c < 12; c++) {
            const uint32_t ko = (uint32_t)c * 64u;
            uint32_t a[2][2][4], bb[3][4];
            ldsm_x4(a[0][0], aB0 + ko);
            ldsm_x4(a[0][1], aB0 + ko + 32);
            ldsm_x4(a[1][0], aB1 + ko);
            ldsm_x4(a[1][1], aB1 + ko + 32);
            ldsm_x4(bb[0], bOff0 + ko);
            ldsm_x4(bb[1], bOff1 + ko);
            ldsm_x4(bb[2], bOff2 + ko);
            const int ng = (c < 8) ? 2 : 3;
            #pragma unroll
            for (int mt = 0; mt < 2; mt++) {
                mma_f16(acc[mt][0],  a[mt][0], bb[0][0], bb[0][1]);
                mma_f16(acc[mt][0],  a[mt][1], bb[0][2], bb[0][3]);
                mma_f16(acc[mt][1],  a[mt][0], bb[1][0], bb[1][1]);
                mma_f16(acc[mt][1],  a[mt][1], bb[1][2], bb[1][3]);
                mma_f16(acc[mt][ng], a[mt][0], bb[2][0], bb[2][1]);
                mma_f16(acc[mt][ng], a[mt][1], bb[2][2], bb[2][3]);
            }
        }

        // (d) epilogue: gates + scatter
        #pragma unroll
        for (int mt = 0; mt < 2; mt++)
            #pragma unroll
            for (int sr = 0; sr < 2; sr++) {
                const long grow = (long)tile * TM + wr * 32 + mt * 16 + gid + sr * 8;
                if (grow < B) {
                    const int e = mt * 2 + sr, f = sr * 2;
                    float rg0 = 1.0f / (1.0f + __expf(-(acc[mt][0][f]     + brz0)));
                    float rg1 = 1.0f / (1.0f + __expf(-(acc[mt][0][f + 1] + brz1)));
                    float zg0 = 1.0f / (1.0f + __expf(-(acc[mt][1][f]     + bzz0)));
                    float zg1 = 1.0f / (1.0f + __expf(-(acc[mt][1][f + 1] + bzz1)));
                    float ng0 = tanhf(acc[mt][2][f]     + bin0 + rg0 * (acc[mt][3][f]     + bhn0));
                    float ng1 = tanhf(acc[mt][2][f + 1] + bin1 + rg1 * (acc[mt][3][f + 1] + bhn1));
                    *(float2*)(out_mem + (long)hnode[e] * H + colb) =
                        make_float2((1.0f - zg0) * ng0 + zg0 * hv[e].x,
                                    (1.0f - zg1) * ng1 + zg1 * hv[e].y);
                }
            }
        if (ch == 0 && tid < TM) {
            long grow = (long)tile * TM + tid;
            if (grow < B) out_lu[node_ids[grow]] = ts[grow];
        }

        // (e) clone STG + last_update clone
        #pragma unroll
        for (int i = 0; i < CLONE_V; i++) {
            if (keep & (1u << i)) {
                long fi = tid + (long)i * NTHREADS;
                long row = ck0 + (fi >> 5);
                *((float4*)(out_mem + row * H) + (fi & 31)) = cv[i];
            }
        }
        if (tid < crows) {
            long row = ck0 + tid;
            if (!g_flag[row]) out_lu[row] = last_update[row];
        }

        // (f/g/h) refill A for next tile
        __syncthreads();
        if (has_next) {
            #pragma unroll
            for (int i = 0; i < 4; i++) {
                int idx = tid + i * NTHREADS;
                int r = idx >> 5, u = idx & 31;
                long grow = (long)next * TM + r; if (grow >= B) grow = B - 1;
                cp16(sh_base + (uint32_t)(A_BYTE + r * WSTB + u * 16),
                     g_X_h + grow * MSG + u * 8);
            }
            CP_COMMIT();
            #pragma unroll
            for (int i = 0; i < 4; i++) {
                int idx = tid + i * NTHREADS;
                int r = idx >> 5, u = idx & 31;
                *(uint2*)(smh + (A_BYTE + r * WSTB + 512) / 2 + u * 4) =
                    make_uint2(pack_h2(ph[i].x, ph[i].y), pack_h2(ph[i].z, ph[i].w));
            }
            CP_WAIT0();
            __syncthreads();
        }
    }

    // leftover clone chunks (CTAs with fewer tiles than chunks)
    for (; tl < nchunks; tl++) {
        const long ck0 = slice0 + (long)tl * CLONE_PT;
        const long crows = (slice_end - ck0 < CLONE_PT) ? slice_end - ck0 : CLONE_PT;
        const long ccount = crows * 32;
        for (long fi = tid; fi < ccount; fi += NTHREADS) {
            long row = ck0 + (fi >> 5);
            if (!g_flag[row])
                *((float4*)(out_mem + row * H) + (fi & 31)) =
                    *((const float4*)(memory + row * H) + (fi & 31));
        }
        if (tid < crows) {
            long row = ck0 + tid;
            if (!g_flag[row]) out_lu[row] = last_update[row];
        }
    }
}

// ---------------------------------------------------------------------------
// Launch. Inputs (metadata order):
//   0 memory [N,128] | 1 last_update [N] | 2 unique_node_ids [B] i32
//   3 unique_messages [B,256] | 4 timestamps [B]
//   5 W_ih [384,256] | 6 W_hh [384,128] | 7 b_ih [384] | 8 b_hh [384]
// ---------------------------------------------------------------------------
extern "C" void kernel_launch(void* const* d_in, const int* in_sizes, int n_in,
                              void* d_out, int out_size) {
    const float* memory      = (const float*)d_in[0];
    const float* last_update = (const float*)d_in[1];
    const int*   node_ids    = (const int*)  d_in[2];
    const float* X           = (const float*)d_in[3];
    const float* ts          = (const float*)d_in[4];
    const float* W_ih        = (const float*)d_in[5];
    const float* W_hh        = (const float*)d_in[6];
    const float* b_ih        = (const float*)d_in[7];
    const float* b_hh        = (const float*)d_in[8];

    const int n_nodes = in_sizes[1];
    const int B       = in_sizes[2];

    float* out_mem = (float*)d_out;
    float* out_lu  = out_mem + (long)n_nodes * H;

    prep_kernel<<<4096, 512>>>(W_ih, W_hh, X, n_nodes, B);
    flag_kernel<<<(B + 511) / 512, 512>>>(node_ids, B);

    cudaFuncSetAttribute(gru_persist_kernel,
                         cudaFuncAttributeMaxDynamicSharedMemorySize, SMEM_BYTES);
    const int grid = 2 * NPAIRS;
    const int ntiles = (B + TM - 1) / TM;
    const int rows_per_cta = (n_nodes + grid - 1) / grid;
    gru_persist_kernel<<<grid, NTHREADS, SMEM_BYTES>>>(
        memory, last_update, node_ids, ts, b_ih, b_hh,
        out_mem, out_lu, B, ntiles, n_nodes, rows_per_cta);
}

// round 12
// speedup vs baseline: 1.2207x; 1.2207x over previous
#include <cuda_runtime.h>
#include <cuda_fp16.h>
#include <cstdint>
#include <math.h>

// ---------------------------------------------------------------------------
// Problem constants
// ---------------------------------------------------------------------------
#define H     128
#define MSG   256
#define TM    32          // rows per tile
#define NSTRIDE 148       // persistent tile stride
#define NTHREADS 256
#define WSTB  784         // smem row stride bytes (384 halves = 768B + 16 pad)

#define SLAB_BYTE (96 * WSTB)              // 75264 : 3 gates x 32 cols (quarter)
#define A_BYTE    SLAB_BYTE
#define SMEM_BYTES (SLAB_BYTE + TM * WSTB) // 100352 -> 2 CTAs/SM

// fp16 weight scratch
__device__ half g_Wih_h[384 * MSG];
__device__ half g_Whh_h[384 * H];

__device__ __forceinline__ void ldsm_x4(uint32_t* r, uint32_t addr) {
    asm volatile("ldmatrix.sync.aligned.m8n8.x4.shared.b16 {%0,%1,%2,%3}, [%4];"
                 : "=r"(r[0]), "=r"(r[1]), "=r"(r[2]), "=r"(r[3]) : "r"(addr));
}
// non-volatile: lets ptxas schedule across the ldsm/mma groups
__device__ __forceinline__ void mma_f16(float* d, const uint32_t* a,
                                        uint32_t b0, uint32_t b1) {
    asm("mma.sync.aligned.m16n8k16.row.col.f32.f16.f16.f32 "
        "{%0,%1,%2,%3}, {%4,%5,%6,%7}, {%8,%9}, {%0,%1,%2,%3};"
        : "+f"(d[0]), "+f"(d[1]), "+f"(d[2]), "+f"(d[3])
        : "r"(a[0]), "r"(a[1]), "r"(a[2]), "r"(a[3]), "r"(b0), "r"(b1));
}
__device__ __forceinline__ uint32_t pack_h2(float x, float y) {
    half2 h = __float22half2_rn(make_float2(x, y));
    return *(uint32_t*)&h;
}
__device__ __forceinline__ void cp16(uint32_t smem_addr, const void* gptr) {
    asm volatile("cp.async.ca.shared.global [%0], [%1], 16;"
                 :: "r"(smem_addr), "l"(gptr) : "memory");
}
#define CP_COMMIT() asm volatile("cp.async.commit_group;" ::: "memory")
#define CP_WAIT0()  asm volatile("cp.async.wait_group 0;" ::: "memory")

// ---------------------------------------------------------------------------
// Prep: convert weights to fp16 scratch (tiny)
// ---------------------------------------------------------------------------
__global__ void prep_kernel(const float* __restrict__ W_ih,
                            const float* __restrict__ W_hh) {
    int i = blockIdx.x * blockDim.x + threadIdx.x;
    int stride = gridDim.x * blockDim.x;
    for (int j = i; j < 384 * MSG + 384 * H; j += stride) {
        if (j < 384 * MSG) g_Wih_h[j] = __float2half_rn(W_ih[j]);
        else               g_Whh_h[j - 384 * MSG] = __float2half_rn(W_hh[j - 384 * MSG]);
    }
}

// ---------------------------------------------------------------------------
// Bulk clone: memory + last_update -> out (85% DRAM)
// ---------------------------------------------------------------------------
__global__ void clone_kernel(const float4* __restrict__ mem_src,
                             float4* __restrict__ mem_dst, long n4m,
                             const float4* __restrict__ lu_src,
                             float4* __restrict__ lu_dst, long n4l) {
    long i = (long)blockIdx.x * blockDim.x + threadIdx.x;
    long stride = (long)gridDim.x * blockDim.x;
    for (long j = i; j < n4m; j += stride) mem_dst[j] = mem_src[j];
    for (long j = i; j < n4l; j += stride) lu_dst[j] = lu_src[j];
}

// ---------------------------------------------------------------------------
// Weight-resident persistent GRU. grid = 4*NSTRIDE; ch = bid&3 -> gate-column
// quarter [ch*32, ch*32+32). 100KB smem -> 2 CTAs/SM -> 16 warps/SM.
// 8 warps: wr = wid>>2 (row group of 16), wn = wid&3 (8-col group).
// Single-buffered A with register prefetch (other CTA covers fill gaps).
// ---------------------------------------------------------------------------
__global__ __launch_bounds__(NTHREADS, 2)
void gru_persist_kernel(const float* __restrict__ memory,
                        const int*   __restrict__ node_ids,
                        const float* __restrict__ X,
                        const float* __restrict__ ts,
                        const float* __restrict__ b_ih,
                        const float* __restrict__ b_hh,
                        float* __restrict__ out_mem,
                        float* __restrict__ out_lu,
                        int B, int ntiles)
{
    extern __shared__ char smc[];
    const uint32_t sh_base = (uint32_t)__cvta_generic_to_shared(smc);

    const int tid  = threadIdx.x;
    const int lane = tid & 31;
    const int wid  = tid >> 5;
    const int wr   = wid >> 2;            // 0..1 : m16 row group (rows wr*16..)
    const int wn   = wid & 3;             // 0..3 : 8-col group within quarter
    const int gid  = lane >> 2;
    const int tig  = lane & 3;
    const int ch   = blockIdx.x & 3;      // column quarter
    const int tstart = blockIdx.x >> 2;

    const int colb = ch * 32 + wn * 8 + tig * 2;
    const float brz0 = b_ih[colb]           + b_hh[colb];
    const float brz1 = b_ih[colb + 1]       + b_hh[colb + 1];
    const float bzz0 = b_ih[128 + colb]     + b_hh[128 + colb];
    const float bzz1 = b_ih[128 + colb + 1] + b_hh[128 + colb + 1];
    const float bin0 = b_ih[256 + colb],     bin1 = b_ih[256 + colb + 1];
    const float bhn0 = b_hh[256 + colb],     bhn1 = b_hh[256 + colb + 1];

    // ---- weight slab: 96 rows x 784B, loaded once ----
    // slab row n: gate = n>>5, weight row = gate*128 + ch*32 + (n&31)
    #pragma unroll
    for (int i = 0; i < 18; i++) {
        int idx = tid + i * NTHREADS;               // 4608 16B-units
        int n = idx / 48, u = idx - n * 48;
        int wrow = ((n >> 5) << 7) + (ch << 5) + (n & 31);
        if (u < 32) cp16(sh_base + (uint32_t)(n * WSTB + u * 16),
                         g_Wih_h + (long)wrow * MSG + u * 8);
        else        cp16(sh_base + (uint32_t)(n * WSTB + 512 + (u - 32) * 16),
                         g_Whh_h + (long)wrow * H + (u - 32) * 8);
    }
    CP_COMMIT();

    // ---- A fill mapping: row r = tid>>3 (0..31), unit base u0 = tid&7 ----
    // X: units 0..31 (512B), h: units 32..47 at byte offset 512.
    const int a_r = tid >> 3, u0 = tid & 7;

    // direct fill of tile 0
    {
        long grow = (long)tstart * TM + a_r; if (grow >= B) grow = B - 1;
        const float4* xs = (const float4*)(X + grow * MSG);
        char* dst = smc + A_BYTE + a_r * WSTB;
        #pragma unroll
        for (int j = 0; j < 4; j++) {
            int u = u0 + j * 8;
            float4 v0 = xs[u * 2], v1 = xs[u * 2 + 1];
            *(uint4*)(dst + u * 16) = make_uint4(pack_h2(v0.x, v0.y), pack_h2(v0.z, v0.w),
                                                 pack_h2(v1.x, v1.y), pack_h2(v1.z, v1.w));
        }
        int node = node_ids[grow];
        const float4* ms = (const float4*)(memory + (long)node * H);
        #pragma unroll
        for (int j = 0; j < 2; j++) {
            int u = u0 + j * 8;
            float4 v0 = ms[u * 2], v1 = ms[u * 2 + 1];
            *(uint4*)(dst + 512 + u * 16) = make_uint4(pack_h2(v0.x, v0.y), pack_h2(v0.z, v0.w),
                                                       pack_h2(v1.x, v1.y), pack_h2(v1.z, v1.w));
        }
    }
    CP_WAIT0();
    __syncthreads();

    // ldsm bases
    const int lane8 = lane & 7, laneA = lane & 15;
    const uint32_t aB0 = sh_base + (uint32_t)A_BYTE
                       + (uint32_t)laneA * WSTB + (uint32_t)(lane >> 4) * 16;
    const uint32_t aB1 = aB0 + 16u * WSTB;
    const uint32_t bOff0 = sh_base + (uint32_t)((wn * 8 + lane8) * WSTB)
                         + (uint32_t)(lane >> 3) * 16;
    const uint32_t bOff1 = bOff0 + 32u * WSTB;
    const uint32_t bOff2 = bOff0 + 64u * WSTB;

    for (int tile = tstart; tile < ntiles; tile += NSTRIDE) {
        const int  next     = tile + NSTRIDE;
        const bool has_next = next < ntiles;

        // prefetch next A tile into packed registers (hidden under k-loop)
        uint32_t pX[16], pH[8];
        if (has_next) {
            long grow = (long)next * TM + a_r; if (grow >= B) grow = B - 1;
            const float4* xs = (const float4*)(X + grow * MSG);
            #pragma unroll
            for (int j = 0; j < 4; j++) {
                int u = u0 + j * 8;
                float4 v0 = xs[u * 2], v1 = xs[u * 2 + 1];
                pX[j * 4]     = pack_h2(v0.x, v0.y); pX[j * 4 + 1] = pack_h2(v0.z, v0.w);
                pX[j * 4 + 2] = pack_h2(v1.x, v1.y); pX[j * 4 + 3] = pack_h2(v1.z, v1.w);
            }
            int node = node_ids[grow];
            const float4* ms = (const float4*)(memory + (long)node * H);
            #pragma unroll
            for (int j = 0; j < 2; j++) {
                int u = u0 + j * 8;
                float4 v0 = ms[u * 2], v1 = ms[u * 2 + 1];
                pH[j * 4]     = pack_h2(v0.x, v0.y); pH[j * 4 + 1] = pack_h2(v0.z, v0.w);
                pH[j * 4 + 2] = pack_h2(v1.x, v1.y); pH[j * 4 + 3] = pack_h2(v1.z, v1.w);
            }
        }

        // epilogue h prefetch
        int    hnode[2];
        float2 hv[2];
        #pragma unroll
        for (int mt = 0; mt < 2; mt++) {
            long grow = (long)tile * TM + wr * 16 + mt * 8 + gid;   // careful: see map below
            (void)grow;
        }
        // row map for epilogue: rows wr*16 + gid (+8 per sr handled via frags)
        #pragma unroll
        for (int sr = 0; sr < 2; sr++) {
            long grow = (long)tile * TM + wr * 16 + gid + sr * 8;
            if (grow >= B) grow = B - 1;
            int node = node_ids[grow];
            hnode[sr] = node;
            hv[sr] = *(const float2*)(memory + (long)node * H + colb);
        }

        // ---- barrier-free K loop over this CTA's m16 tile (rows wr*16..) ----
        float acc[4][4];   // 0=r 1=z 2=i_n 3=h_n
        #pragma unroll
        for (int g = 0; g < 4; g++)
            #pragma unroll
            for (int j = 0; j < 4; j++) acc[g][j] = 0.f;

        const uint32_t aB = (wr == 0) ? aB0 : aB1;
        #pragma unroll
        for (int c = 0; c < 12; c++) {
            const uint32_t ko = (uint32_t)c * 64u;
            uint32_t a[2][4], bb[3][4];
            ldsm_x4(a[0], aB + ko);
            ldsm_x4(a[1], aB + ko + 32);
            ldsm_x4(bb[0], bOff0 + ko);
            ldsm_x4(bb[1], bOff1 + ko);
            ldsm_x4(bb[2], bOff2 + ko);
            const int ng = (c < 8) ? 2 : 3;
            mma_f16(acc[0],  a[0], bb[0][0], bb[0][1]);
            mma_f16(acc[0],  a[1], bb[0][2], bb[0][3]);
            mma_f16(acc[1],  a[0], bb[1][0], bb[1][1]);
            mma_f16(acc[1],  a[1], bb[1][2], bb[1][3]);
            mma_f16(acc[ng], a[0], bb[2][0], bb[2][1]);
            mma_f16(acc[ng], a[1], bb[2][2], bb[2][3]);
        }

        // ---- epilogue: gates + scatter ----
        #pragma unroll
        for (int sr = 0; sr < 2; sr++) {
            const long grow = (long)tile * TM + wr * 16 + gid + sr * 8;
            if (grow < B) {
                const int f = sr * 2;
                float rg0 = 1.0f / (1.0f + __expf(-(acc[0][f]     + brz0)));
                float rg1 = 1.0f / (1.0f + __expf(-(acc[0][f + 1] + brz1)));
                float zg0 = 1.0f / (1.0f + __expf(-(acc[1][f]     + bzz0)));
                float zg1 = 1.0f / (1.0f + __expf(-(acc[1][f + 1] + bzz1)));
                float ng0 = tanhf(acc[2][f]     + bin0 + rg0 * (acc[3][f]     + bhn0));
                float ng1 = tanhf(acc[2][f + 1] + bin1 + rg1 * (acc[3][f + 1] + bhn1));
                *(float2*)(out_mem + (long)hnode[sr] * H + colb) =
                    make_float2((1.0f - zg0) * ng0 + zg0 * hv[sr].x,
                                (1.0f - zg1) * ng1 + zg1 * hv[sr].y);
            }
        }
        if (ch == 0 && tid < TM) {
            long grow = (long)tile * TM + tid;
            if (grow < B) out_lu[node_ids[grow]] = ts[grow];
        }

        // ---- store prefetched A (single buffer: barrier, STS, barrier) ----
        __syncthreads();
        if (has_next) {
            char* dst = smc + A_BYTE + a_r * WSTB;
            #pragma unroll
            for (int j = 0; j < 4; j++) {
                int u = u0 + j * 8;
                *(uint4*)(dst + u * 16) =
                    make_uint4(pX[j * 4], pX[j * 4 + 1], pX[j * 4 + 2], pX[j * 4 + 3]);
            }
            #pragma unroll
            for (int j = 0; j < 2; j++) {
                int u = u0 + j * 8;
                *(uint4*)(dst + 512 + u * 16) =
                    make_uint4(pH[j * 4], pH[j * 4 + 1], pH[j * 4 + 2], pH[j * 4 + 3]);
            }
            __syncthreads();
        }
    }
}

// ---------------------------------------------------------------------------
// Launch. Inputs (metadata order):
//   0 memory [N,128] | 1 last_update [N] | 2 unique_node_ids [B] i32
//   3 unique_messages [B,256] | 4 timestamps [B]
//   5 W_ih [384,256] | 6 W_hh [384,128] | 7 b_ih [384] | 8 b_hh [384]
// Output: concat(updated_memory [N*128], updated_last_update [N]) f32
// ---------------------------------------------------------------------------
extern "C" void kernel_launch(void* const* d_in, const int* in_sizes, int n_in,
                              void* d_out, int out_size) {
    const float* memory      = (const float*)d_in[0];
    const float* last_update = (const float*)d_in[1];
    const int*   node_ids    = (const int*)  d_in[2];
    const float* X           = (const float*)d_in[3];
    const float* ts          = (const float*)d_in[4];
    const float* W_ih        = (const float*)d_in[5];
    const float* W_hh        = (const float*)d_in[6];
    const float* b_ih        = (const float*)d_in[7];
    const float* b_hh        = (const float*)d_in[8];

    const int n_nodes = in_sizes[1];
    const int B       = in_sizes[2];

    float* out_mem = (float*)d_out;
    float* out_lu  = out_mem + (long)n_nodes * H;

    // 1) fp16 weight conversion
    prep_kernel<<<288, 512>>>(W_ih, W_hh);
    // 2) full clone (near-DRAM-roofline)
    {
        long n4m = (long)n_nodes * H / 4;
        long n4l = (long)n_nodes / 4;
        clone_kernel<<<16384, 256>>>((const float4*)memory, (float4*)out_mem, n4m,
                                     (const float4*)last_update, (float4*)out_lu, n4l);
    }
    // 3) weight-resident persistent GRU, 2 CTAs/SM (overwrites updated rows)
    {
        cudaFuncSetAttribute(gru_persist_kernel,
                             cudaFuncAttributeMaxDynamicSharedMemorySize, SMEM_BYTES);
        int ntiles = (B + TM - 1) / TM;
        gru_persist_kernel<<<4 * NSTRIDE, NTHREADS, SMEM_BYTES>>>(
            memory, node_ids, X, ts, b_ih, b_hh, out_mem, out_lu, B, ntiles);
    }
}

// round 13
// speedup vs baseline: 1.2696x; 1.0401x over previous
#include <cuda_runtime.h>
#include <cuda_fp16.h>
#include <cstdint>
#include <math.h>

// ---------------------------------------------------------------------------
// Problem constants
// ---------------------------------------------------------------------------
#define H     128
#define MSG   256
#define TM    32          // rows per tile
#define NSTRIDE 148       // persistent tile stride
#define NTHREADS 256
#define WSTB  784         // smem row stride bytes (384 halves = 768B + 16 pad)

#define SLAB_BYTE (96 * WSTB)              // 75264 : 3 gates x 32 cols (quarter)
#define A_BYTE    SLAB_BYTE
#define SMEM_BYTES (SLAB_BYTE + TM * WSTB) // 100352 -> 2 CTAs/SM

// fp16 weight scratch + updated-row flags
__device__ half          g_Wih_h[384 * MSG];
__device__ half          g_Whh_h[384 * H];
__device__ unsigned char g_flag[1 << 20];

__device__ __forceinline__ void ldsm_x4(uint32_t* r, uint32_t addr) {
    asm volatile("ldmatrix.sync.aligned.m8n8.x4.shared.b16 {%0,%1,%2,%3}, [%4];"
                 : "=r"(r[0]), "=r"(r[1]), "=r"(r[2]), "=r"(r[3]) : "r"(addr));
}
__device__ __forceinline__ void mma_f16(float* d, const uint32_t* a,
                                        uint32_t b0, uint32_t b1) {
    asm("mma.sync.aligned.m16n8k16.row.col.f32.f16.f16.f32 "
        "{%0,%1,%2,%3}, {%4,%5,%6,%7}, {%8,%9}, {%0,%1,%2,%3};"
        : "+f"(d[0]), "+f"(d[1]), "+f"(d[2]), "+f"(d[3])
        : "r"(a[0]), "r"(a[1]), "r"(a[2]), "r"(a[3]), "r"(b0), "r"(b1));
}
__device__ __forceinline__ uint32_t pack_h2(float x, float y) {
    half2 h = __float22half2_rn(make_float2(x, y));
    return *(uint32_t*)&h;
}
__device__ __forceinline__ void cp16(uint32_t smem_addr, const void* gptr) {
    asm volatile("cp.async.ca.shared.global [%0], [%1], 16;"
                 :: "r"(smem_addr), "l"(gptr) : "memory");
}
#define CP_COMMIT() asm volatile("cp.async.commit_group;" ::: "memory")
#define CP_WAIT0()  asm volatile("cp.async.wait_group 0;" ::: "memory")

// ---------------------------------------------------------------------------
// Prep: zero flags + convert weights to fp16 scratch
// ---------------------------------------------------------------------------
__global__ void prep_kernel(const float* __restrict__ W_ih,
                            const float* __restrict__ W_hh, int n_nodes) {
    int i = blockIdx.x * blockDim.x + threadIdx.x;
    int stride = gridDim.x * blockDim.x;
    for (int j = i; j < n_nodes; j += stride) g_flag[j] = 0;
    for (int j = i; j < 384 * MSG + 384 * H; j += stride) {
        if (j < 384 * MSG) g_Wih_h[j] = __float2half_rn(W_ih[j]);
        else               g_Whh_h[j - 384 * MSG] = __float2half_rn(W_hh[j - 384 * MSG]);
    }
}
__global__ void flag_kernel(const int* __restrict__ node_ids, int B) {
    int i = blockIdx.x * blockDim.x + threadIdx.x;
    if (i < B) g_flag[node_ids[i]] = 1;
}

// ---------------------------------------------------------------------------
// Selective clone (skips flagged rows) — runs CONCURRENTLY with the GRU
// kernel on a forked stream; writes are disjoint from the GRU scatter.
// ---------------------------------------------------------------------------
__global__ void clone_sel_kernel(const float* __restrict__ memory,
                                 const float* __restrict__ last_update,
                                 float* __restrict__ out_mem,
                                 float* __restrict__ out_lu,
                                 int n_nodes) {
    const int lane = threadIdx.x & 31;
    const long warp = (long)(blockIdx.x * (blockDim.x >> 5)) + (threadIdx.x >> 5);
    const long nwarps = (long)gridDim.x * (blockDim.x >> 5);
    for (long row = warp; row < n_nodes; row += nwarps) {
        if (!g_flag[row]) {
            *((float4*)(out_mem + row * H) + lane) =
                *((const float4*)(memory + row * H) + lane);
        }
    }
    const long gtid = (long)blockIdx.x * blockDim.x + threadIdx.x;
    const long gthreads = (long)gridDim.x * blockDim.x;
    for (long i = gtid; i < n_nodes; i += gthreads)
        if (!g_flag[i]) out_lu[i] = last_update[i];
}

// ---------------------------------------------------------------------------
// Weight-resident persistent GRU (unchanged from round 12: 539us proven).
// grid = 4*NSTRIDE; ch = bid&3 -> gate-column quarter. 2 CTAs/SM.
// ---------------------------------------------------------------------------
__global__ __launch_bounds__(NTHREADS, 2)
void gru_persist_kernel(const float* __restrict__ memory,
                        const int*   __restrict__ node_ids,
                        const float* __restrict__ X,
                        const float* __restrict__ ts,
                        const float* __restrict__ b_ih,
                        const float* __restrict__ b_hh,
                        float* __restrict__ out_mem,
                        float* __restrict__ out_lu,
                        int B, int ntiles)
{
    extern __shared__ char smc[];
    const uint32_t sh_base = (uint32_t)__cvta_generic_to_shared(smc);

    const int tid  = threadIdx.x;
    const int lane = tid & 31;
    const int wid  = tid >> 5;
    const int wr   = wid >> 2;
    const int wn   = wid & 3;
    const int gid  = lane >> 2;
    const int tig  = lane & 3;
    const int ch   = blockIdx.x & 3;
    const int tstart = blockIdx.x >> 2;

    const int colb = ch * 32 + wn * 8 + tig * 2;
    const float brz0 = b_ih[colb]           + b_hh[colb];
    const float brz1 = b_ih[colb + 1]       + b_hh[colb + 1];
    const float bzz0 = b_ih[128 + colb]     + b_hh[128 + colb];
    const float bzz1 = b_ih[128 + colb + 1] + b_hh[128 + colb + 1];
    const float bin0 = b_ih[256 + colb],     bin1 = b_ih[256 + colb + 1];
    const float bhn0 = b_hh[256 + colb],     bhn1 = b_hh[256 + colb + 1];

    #pragma unroll
    for (int i = 0; i < 18; i++) {
        int idx = tid + i * NTHREADS;
        int n = idx / 48, u = idx - n * 48;
        int wrow = ((n >> 5) << 7) + (ch << 5) + (n & 31);
        if (u < 32) cp16(sh_base + (uint32_t)(n * WSTB + u * 16),
                         g_Wih_h + (long)wrow * MSG + u * 8);
        else        cp16(sh_base + (uint32_t)(n * WSTB + 512 + (u - 32) * 16),
                         g_Whh_h + (long)wrow * H + (u - 32) * 8);
    }
    CP_COMMIT();

    const int a_r = tid >> 3, u0 = tid & 7;
    {
        long grow = (long)tstart * TM + a_r; if (grow >= B) grow = B - 1;
        const float4* xs = (const float4*)(X + grow * MSG);
        char* dst = smc + A_BYTE + a_r * WSTB;
        #pragma unroll
        for (int j = 0; j < 4; j++) {
            int u = u0 + j * 8;
            float4 v0 = xs[u * 2], v1 = xs[u * 2 + 1];
            *(uint4*)(dst + u * 16) = make_uint4(pack_h2(v0.x, v0.y), pack_h2(v0.z, v0.w),
                                                 pack_h2(v1.x, v1.y), pack_h2(v1.z, v1.w));
        }
        int node = node_ids[grow];
        const float4* ms = (const float4*)(memory + (long)node * H);
        #pragma unroll
        for (int j = 0; j < 2; j++) {
            int u = u0 + j * 8;
            float4 v0 = ms[u * 2], v1 = ms[u * 2 + 1];
            *(uint4*)(dst + 512 + u * 16) = make_uint4(pack_h2(v0.x, v0.y), pack_h2(v0.z, v0.w),
                                                       pack_h2(v1.x, v1.y), pack_h2(v1.z, v1.w));
        }
    }
    CP_WAIT0();
    __syncthreads();

    const int lane8 = lane & 7, laneA = lane & 15;
    const uint32_t aB0 = sh_base + (uint32_t)A_BYTE
                       + (uint32_t)laneA * WSTB + (uint32_t)(lane >> 4) * 16;
    const uint32_t aB1 = aB0 + 16u * WSTB;
    const uint32_t bOff0 = sh_base + (uint32_t)((wn * 8 + lane8) * WSTB)
                         + (uint32_t)(lane >> 3) * 16;
    const uint32_t bOff1 = bOff0 + 32u * WSTB;
    const uint32_t bOff2 = bOff0 + 64u * WSTB;

    for (int tile = tstart; tile < ntiles; tile += NSTRIDE) {
        const int  next     = tile + NSTRIDE;
        const bool has_next = next < ntiles;

        uint32_t pX[16], pH[8];
        if (has_next) {
            long grow = (long)next * TM + a_r; if (grow >= B) grow = B - 1;
            const float4* xs = (const float4*)(X + grow * MSG);
            #pragma unroll
            for (int j = 0; j < 4; j++) {
                int u = u0 + j * 8;
                float4 v0 = xs[u * 2], v1 = xs[u * 2 + 1];
                pX[j * 4]     = pack_h2(v0.x, v0.y); pX[j * 4 + 1] = pack_h2(v0.z, v0.w);
                pX[j * 4 + 2] = pack_h2(v1.x, v1.y); pX[j * 4 + 3] = pack_h2(v1.z, v1.w);
            }
            int node = node_ids[grow];
            const float4* ms = (const float4*)(memory + (long)node * H);
            #pragma unroll
            for (int j = 0; j < 2; j++) {
                int u = u0 + j * 8;
                float4 v0 = ms[u * 2], v1 = ms[u * 2 + 1];
                pH[j * 4]     = pack_h2(v0.x, v0.y); pH[j * 4 + 1] = pack_h2(v0.z, v0.w);
                pH[j * 4 + 2] = pack_h2(v1.x, v1.y); pH[j * 4 + 3] = pack_h2(v1.z, v1.w);
            }
        }

        int    hnode[2];
        float2 hv[2];
        #pragma unroll
        for (int sr = 0; sr < 2; sr++) {
            long grow = (long)tile * TM + wr * 16 + gid + sr * 8;
            if (grow >= B) grow = B - 1;
            int node = node_ids[grow];
            hnode[sr] = node;
            hv[sr] = *(const float2*)(memory + (long)node * H + colb);
        }

        float acc[4][4];
        #pragma unroll
        for (int g = 0; g < 4; g++)
            #pragma unroll
            for (int j = 0; j < 4; j++) acc[g][j] = 0.f;

        const uint32_t aB = (wr == 0) ? aB0 : aB1;
        #pragma unroll
        for (int c = 0; c < 12; c++) {
            const uint32_t ko = (uint32_t)c * 64u;
            uint32_t a[2][4], bb[3][4];
            ldsm_x4(a[0], aB + ko);
            ldsm_x4(a[1], aB + ko + 32);
            ldsm_x4(bb[0], bOff0 + ko);
            ldsm_x4(bb[1], bOff1 + ko);
            ldsm_x4(bb[2], bOff2 + ko);
            const int ng = (c < 8) ? 2 : 3;
            mma_f16(acc[0],  a[0], bb[0][0], bb[0][1]);
            mma_f16(acc[0],  a[1], bb[0][2], bb[0][3]);
            mma_f16(acc[1],  a[0], bb[1][0], bb[1][1]);
            mma_f16(acc[1],  a[1], bb[1][2], bb[1][3]);
            mma_f16(acc[ng], a[0], bb[2][0], bb[2][1]);
            mma_f16(acc[ng], a[1], bb[2][2], bb[2][3]);
        }

        #pragma unroll
        for (int sr = 0; sr < 2; sr++) {
            const long grow = (long)tile * TM + wr * 16 + gid + sr * 8;
            if (grow < B) {
                const int f = sr * 2;
                float rg0 = 1.0f / (1.0f + __expf(-(acc[0][f]     + brz0)));
                float rg1 = 1.0f / (1.0f + __expf(-(acc[0][f + 1] + brz1)));
                float zg0 = 1.0f / (1.0f + __expf(-(acc[1][f]     + bzz0)));
                float zg1 = 1.0f / (1.0f + __expf(-(acc[1][f + 1] + bzz1)));
                float ng0 = tanhf(acc[2][f]     + bin0 + rg0 * (acc[3][f]     + bhn0));
                float ng1 = tanhf(acc[2][f + 1] + bin1 + rg1 * (acc[3][f + 1] + bhn1));
                *(float2*)(out_mem + (long)hnode[sr] * H + colb) =
                    make_float2((1.0f - zg0) * ng0 + zg0 * hv[sr].x,
                                (1.0f - zg1) * ng1 + zg1 * hv[sr].y);
            }
        }
        if (ch == 0 && tid < TM) {
            long grow = (long)tile * TM + tid;
            if (grow < B) out_lu[node_ids[grow]] = ts[grow];
        }

        __syncthreads();
        if (has_next) {
            char* dst = smc + A_BYTE + a_r * WSTB;
            #pragma unroll
            for (int j = 0; j < 4; j++) {
                int u = u0 + j * 8;
                *(uint4*)(dst + u * 16) =
                    make_uint4(pX[j * 4], pX[j * 4 + 1], pX[j * 4 + 2], pX[j * 4 + 3]);
            }
            #pragma unroll
            for (int j = 0; j < 2; j++) {
                int u = u0 + j * 8;
                *(uint4*)(dst + 512 + u * 16) =
                    make_uint4(pH[j * 4], pH[j * 4 + 1], pH[j * 4 + 2], pH[j * 4 + 3]);
            }
            __syncthreads();
        }
    }
}

// ---------------------------------------------------------------------------
// Launch. Forked-stream graph:
//   default: prep -> flag -> [e1] -> gru ------------- [wait e2]
//   s2:                      [wait e1] -> clone_sel -> [e2]
// clone and gru run concurrently; writes disjoint via g_flag.
// ---------------------------------------------------------------------------
extern "C" void kernel_launch(void* const* d_in, const int* in_sizes, int n_in,
                              void* d_out, int out_size) {
    const float* memory      = (const float*)d_in[0];
    const float* last_update = (const float*)d_in[1];
    const int*   node_ids    = (const int*)  d_in[2];
    const float* X           = (const float*)d_in[3];
    const float* ts          = (const float*)d_in[4];
    const float* W_ih        = (const float*)d_in[5];
    const float* W_hh        = (const float*)d_in[6];
    const float* b_ih        = (const float*)d_in[7];
    const float* b_hh        = (const float*)d_in[8];

    const int n_nodes = in_sizes[1];
    const int B       = in_sizes[2];

    float* out_mem = (float*)d_out;
    float* out_lu  = out_mem + (long)n_nodes * H;

    // one-time resources (first call is the non-captured correctness run)
    static cudaStream_t s2 = nullptr;
    static cudaEvent_t  e1 = nullptr, e2 = nullptr;
    if (s2 == nullptr) {
        cudaStreamCreateWithFlags(&s2, cudaStreamNonBlocking);
        cudaEventCreateWithFlags(&e1, cudaEventDisableTiming);
        cudaEventCreateWithFlags(&e2, cudaEventDisableTiming);
        cudaFuncSetAttribute(gru_persist_kernel,
                             cudaFuncAttributeMaxDynamicSharedMemorySize, SMEM_BYTES);
    }

    prep_kernel<<<512, 512>>>(W_ih, W_hh, n_nodes);
    flag_kernel<<<(B + 511) / 512, 512>>>(node_ids, B);

    cudaEventRecord(e1, 0);
    cudaStreamWaitEvent(s2, e1, 0);
    clone_sel_kernel<<<4096, 256, 0, s2>>>(memory, last_update,
                                           out_mem, out_lu, n_nodes);
    cudaEventRecord(e2, s2);

    {
        int ntiles = (B + TM - 1) / TM;
        gru_persist_kernel<<<4 * NSTRIDE, NTHREADS, SMEM_BYTES>>>(
            memory, node_ids, X, ts, b_ih, b_hh, out_mem, out_lu, B, ntiles);
    }
    cudaStreamWaitEvent(0, e2, 0);
}